// round 9
// baseline (speedup 1.0000x reference)
#include <cuda_runtime.h>
#include <cuda_bf16.h>

// ---------------------------------------------------------------------------
// ASCC continuous conv, v7 (register stage A + k-split stage B):
//   L0: count_edges + build_kcanon (merged)
//   L1: decoupled-lookback scan
//   L2: build_records (SoA: w4 + (sender, t0)); re-zeros count/pub for replay
//   L3: fused kernel, 32 nodes/CTA, 512 threads, 1 CTA/SM:
//       Stage A: warp owns 2 adjacent nodes; A accumulated in REGISTERS
//                (warp-uniform switch on t0 -> constant-indexed FFMAs);
//                dual-stream + depth-4 feature pipeline; A written to smem
//                once, bf16 hi/lo packed (no smem RMW, no convert pass).
//       Stage B: warp (mtile, kgroup) owns 8 K-slices x all 8 n-tiles
//                (A fragments read exactly once); partial D reduced via
//                padded smem buffer; m16n8k16 bf16 x3 split precision.
// ---------------------------------------------------------------------------

#define NMAX    50048
#define EMAX    800000
#define INC     64
#define OUTC    64
#define MTILE   32
#define THREADS 512
#define APAD    1032            // floats per node row in smem A tile
#define CHUNK   512             // one staged edge per thread
#define FDEPTH  4               // per stream (2 streams)
#define NBMAX   64

#define KSLICES 64
#define NTILES  8

#define SMEM_FLOATS (MTILE * APAD)                       // 33024 floats
#define SMEM_BYTES  (SMEM_FLOATS * 4 + CHUNK * 16 + CHUNK * 8)

#define PARTW   1152            // floats per warp partial region (32 lanes*36)

#define KC_BLOCKS 64            // 16384 / 256

__device__ float4 g_w   [EMAX];
__device__ int2   g_meta[EMAX];          // (sender, t0)
__device__ int    g_count  [NMAX];
__device__ int    g_offsets[NMAX + 1];
__device__ int    g_cursor [NMAX];
__device__ int    g_pub    [NBMAX];
__device__ uint4  g_kc[KSLICES * NTILES * 32];

#define PUB_FLAG 0x40000000

// ---------------------------------------------------------------------------
__device__ __forceinline__ float kfull_val(const float* __restrict__ kernelW,
                                           int k, int nn) {
    int tap = k >> 6, i = k & 63;
    int tx = tap >> 2, ty = tap & 3;
    if (ty < 2) return  kernelW[(tx * 2 + ty) * 4096 + i * 64 + nn];
    else        return -kernelW[((3 - tx) * 2 + (3 - ty)) * 4096 + i * 64 + nn];
}

__global__ void count_and_kcanon(const int* __restrict__ receivers, int e,
                                 int cntBlocks,
                                 const float* __restrict__ kernelW) {
    int b = blockIdx.x;
    if (b < cntBlocks) {
        int i = b * 256 + threadIdx.x;
        if (i < e) atomicAdd(&g_count[receivers[i]], 1);
        return;
    }
    int idx = (b - cntBlocks) * 256 + threadIdx.x;
    if (idx >= KSLICES * NTILES * 32) return;
    int lane = idx & 31;
    int nt   = (idx >> 5) & 7;
    int s    = idx >> 8;
    int g = lane >> 2, c = lane & 3;
    int nn = nt * 8 + g;
    int k0 = s * 16 + 2 * c;

    float v0 = kfull_val(kernelW, k0,     nn);
    float v1 = kfull_val(kernelW, k0 + 1, nn);
    float v2 = kfull_val(kernelW, k0 + 8, nn);
    float v3 = kfull_val(kernelW, k0 + 9, nn);

    __nv_bfloat162 h01 = __floats2bfloat162_rn(v0, v1);
    __nv_bfloat162 h23 = __floats2bfloat162_rn(v2, v3);
    float h0 = __bfloat162float(__low2bfloat16(h01));
    float h1 = __bfloat162float(__high2bfloat16(h01));
    float h2 = __bfloat162float(__low2bfloat16(h23));
    float h3 = __bfloat162float(__high2bfloat16(h23));
    __nv_bfloat162 l01 = __floats2bfloat162_rn(v0 - h0, v1 - h1);
    __nv_bfloat162 l23 = __floats2bfloat162_rn(v2 - h2, v3 - h3);

    uint4 kv;
    kv.x = *reinterpret_cast<unsigned*>(&h01);
    kv.y = *reinterpret_cast<unsigned*>(&h23);
    kv.z = *reinterpret_cast<unsigned*>(&l01);
    kv.w = *reinterpret_cast<unsigned*>(&l23);
    g_kc[idx] = kv;
}

// ---------------------------------------------------------------------------
__global__ void scan_lookback(int n, int nb) {
    __shared__ int wsum[32];
    __shared__ int rsum[32];
    int tid = threadIdx.x, lane = tid & 31, wid = tid >> 5;
    int b = blockIdx.x;
    int i = b * 1024 + tid;
    int v = (i < n) ? g_count[i] : 0;
    int x = v;
    #pragma unroll
    for (int d = 1; d < 32; d <<= 1) {
        int y = __shfl_up_sync(0xFFFFFFFFu, x, d);
        if (lane >= d) x += y;
    }
    if (lane == 31) wsum[wid] = x;
    __syncthreads();
    if (wid == 0) {
        int s = wsum[lane];
        #pragma unroll
        for (int d = 1; d < 32; d <<= 1) {
            int y = __shfl_up_sync(0xFFFFFFFFu, s, d);
            if (lane >= d) s += y;
        }
        wsum[lane] = s;
    }
    __syncthreads();
    int aggregate = wsum[31];

    if (tid == 0) atomicExch(&g_pub[b], aggregate | PUB_FLAG);

    int myprev = 0;
    if (tid < b) {
        int pv = atomicAdd(&g_pub[tid], 0);
        while (!(pv & PUB_FLAG)) {
            __nanosleep(64);
            pv = atomicAdd(&g_pub[tid], 0);
        }
        myprev = pv & (PUB_FLAG - 1);
    }
    #pragma unroll
    for (int d = 16; d > 0; d >>= 1)
        myprev += __shfl_down_sync(0xFFFFFFFFu, myprev, d);
    if (lane == 0) rsum[wid] = myprev;
    __syncthreads();
    if (wid == 0) {
        int t = rsum[lane];
        #pragma unroll
        for (int d = 16; d > 0; d >>= 1)
            t += __shfl_down_sync(0xFFFFFFFFu, t, d);
        rsum[0] = t;
    }
    __syncthreads();
    int exclBlock = rsum[0];

    int excl = exclBlock + (wid ? wsum[wid - 1] : 0) + (x - v);
    if (i < n) { g_offsets[i] = excl; g_cursor[i] = excl; }
    if (b == nb - 1 && tid == 0) g_offsets[n] = exclBlock + aggregate;
}

// ---------------------------------------------------------------------------
__global__ void build_records(const int*   __restrict__ receivers,
                              const int*   __restrict__ senders,
                              const float* __restrict__ relpos,
                              const float* __restrict__ wsp,
                              int e) {
    int i = blockIdx.x * blockDim.x + threadIdx.x;
    if (i < NMAX)  g_count[i] = 0;
    if (i < NBMAX) g_pub[i]   = 0;
    if (i >= e) return;
    float ws = wsp[0];
    float rx = relpos[2 * i], ry = relpos[2 * i + 1];
    float ux = fminf(fmaxf(rx / ws, -1.0f), 1.0f);
    float uy = fminf(fmaxf(ry / ws, -1.0f), 1.0f);
    float gx = (ux + 1.0f) * 1.5f;
    float gy = (uy + 1.0f) * 1.5f;
    float x0f = fminf(fmaxf(floorf(gx), 0.0f), 2.0f);
    float y0f = fminf(fmaxf(floorf(gy), 0.0f), 2.0f);
    float fx = gx - x0f, fy = gy - y0f;
    float r2 = ux * ux + uy * uy;
    float wm = fmaxf(1.0f - r2, 0.0f);
    float win = wm * wm * wm;
    int x0 = (int)x0f, y0 = (int)y0f;
    int t0 = x0 * 4 + y0;

    float4 w = make_float4((1.0f - fx) * (1.0f - fy) * win,
                           (1.0f - fx) * fy          * win,
                           fx          * (1.0f - fy) * win,
                           fx          * fy          * win);

    int r = receivers[i];
    int slot = atomicAdd(&g_cursor[r], 1);
    g_w[slot]    = w;
    g_meta[slot] = make_int2(senders[i], t0);
}

// ---------------------------------------------------------------------------
__device__ __forceinline__ void mma16816(float* d,
        unsigned a0, unsigned a1, unsigned a2, unsigned a3,
        unsigned b0, unsigned b1) {
    asm volatile(
        "mma.sync.aligned.m16n8k16.row.col.f32.bf16.bf16.f32 "
        "{%0,%1,%2,%3}, {%4,%5,%6,%7}, {%8,%9}, {%0,%1,%2,%3};"
        : "+f"(d[0]), "+f"(d[1]), "+f"(d[2]), "+f"(d[3])
        : "r"(a0), "r"(a1), "r"(a2), "r"(a3), "r"(b0), "r"(b1));
}

// warp-uniform switch on t0; all register indices compile-time constant
#define ACC(t, ww) { a[t].x += (ww) * f.x; a[t].y += (ww) * f.y; }
#define TAPCASE(T) case T: ACC(T, w4.x); ACC((T)+1, w4.y); \
                           ACC((T)+4, w4.z); ACC((T)+5, w4.w); break;
__device__ __forceinline__ void apply_reg(float2* a, int t0,
                                          float4 w4, float2 f) {
    switch (t0) {
        TAPCASE(0) TAPCASE(1) TAPCASE(2)
        TAPCASE(4) TAPCASE(5) TAPCASE(6)
        TAPCASE(8) TAPCASE(9) TAPCASE(10)
        default: break;
    }
}

__global__ __launch_bounds__(THREADS, 1)
void fused_conv_kernel(const float* __restrict__ features,
                       const float* __restrict__ bias,
                       float*       __restrict__ out,
                       int n) {
    extern __shared__ float smem[];
    float*  As = smem;                                   // MTILE * APAD
    float4* ws = (float4*)(smem + SMEM_FLOATS);          // CHUNK
    int2*   ms = (int2*)((char*)ws + CHUNK * 16);        // CHUNK

    int tid  = threadIdx.x;
    int lane = tid & 31, wid = tid >> 5;                 // 16 warps
    int nodeBase = blockIdx.x * MTILE;

    int n0 = min(nodeBase + 2 * wid,     n);
    int n1 = min(nodeBase + 2 * wid + 1, n);
    int n2 = min(nodeBase + 2 * wid + 2, n);
    int s   = g_offsets[n0];
    int mid = g_offsets[n1];
    int e2  = g_offsets[n2];

    int o0 = g_offsets[nodeBase];
    int oE = g_offsets[min(nodeBase + MTILE, n)];

    // register accumulators: 2 nodes x 16 taps x channel pair (2*lane)
    float2 a0[16], a1[16];
    #pragma unroll
    for (int t = 0; t < 16; ++t) {
        a0[t] = make_float2(0.f, 0.f);
        a1[t] = make_float2(0.f, 0.f);
    }

    // stage chunk 0 into registers (1 edge/thread)
    float4 rw = make_float4(0.f, 0.f, 0.f, 0.f);
    int2   rm = make_int2(0, 0);
    if (o0 + tid < oE) { rw = g_w[o0 + tid]; rm = g_meta[o0 + tid]; }

    // -------- Stage A: dual-stream register accumulation --------
    for (int cs = o0; cs < oE; cs += CHUNK) {
        if (cs + tid < oE) { ws[tid] = rw; ms[tid] = rm; }
        __syncthreads();
        int nx = cs + CHUNK + tid;
        if (nx < oE) { rw = g_w[nx]; rm = g_meta[nx]; }

        int ce = min(cs + CHUNK, oE);
        int ja = max(s,   cs), ea = min(mid, ce);   // stream A -> a0
        int jb = max(mid, cs), eb = min(e2,  ce);   // stream B -> a1
        int cnt = max(ea - ja, eb - jb);
        if (cnt > 0) {
            float2 fa[FDEPTH], fb[FDEPTH];
            #pragma unroll
            for (int d = 0; d < FDEPTH; ++d) {
                if (ja + d < ea)
                    fa[d] = *(const float2*)(features +
                        (size_t)ms[ja + d - cs].x * INC + lane * 2);
                if (jb + d < eb)
                    fb[d] = *(const float2*)(features +
                        (size_t)ms[jb + d - cs].x * INC + lane * 2);
            }
            for (int k = 0; k < cnt; ++k) {
                int d = k & (FDEPTH - 1);
                if (ja + k < ea) {
                    int li = ja + k - cs;
                    float4 w4 = ws[li];
                    int    t0 = ms[li].y;
                    float2 f  = fa[d];
                    int jn = ja + k + FDEPTH;
                    if (jn < ea)
                        fa[d] = *(const float2*)(features +
                            (size_t)ms[jn - cs].x * INC + lane * 2);
                    apply_reg(a0, t0, w4, f);
                }
                if (jb + k < eb) {
                    int li = jb + k - cs;
                    float4 w4 = ws[li];
                    int    t0 = ms[li].y;
                    float2 f  = fb[d];
                    int jn = jb + k + FDEPTH;
                    if (jn < eb)
                        fb[d] = *(const float2*)(features +
                            (size_t)ms[jn - cs].x * INC + lane * 2);
                    apply_reg(a1, t0, w4, f);
                }
            }
        }
        __syncthreads();
    }

    // -------- write A to smem, bf16 hi/lo packed (one pass, no RMW) --------
    {
        uint2* Am0 = (uint2*)(As + (2 * wid)     * APAD) ;
        uint2* Am1 = (uint2*)(As + (2 * wid + 1) * APAD);
        #pragma unroll
        for (int t = 0; t < 16; ++t) {
            float2 v = a0[t];
            __nv_bfloat162 h = __floats2bfloat162_rn(v.x, v.y);
            float hx = __bfloat162float(__low2bfloat16(h));
            float hy = __bfloat162float(__high2bfloat16(h));
            __nv_bfloat162 l = __floats2bfloat162_rn(v.x - hx, v.y - hy);
            uint2 wv;
            wv.x = *reinterpret_cast<unsigned*>(&h);
            wv.y = *reinterpret_cast<unsigned*>(&l);
            Am0[t * 32 + lane] = wv;

            v = a1[t];
            h = __floats2bfloat162_rn(v.x, v.y);
            hx = __bfloat162float(__low2bfloat16(h));
            hy = __bfloat162float(__high2bfloat16(h));
            l = __floats2bfloat162_rn(v.x - hx, v.y - hy);
            wv.x = *reinterpret_cast<unsigned*>(&h);
            wv.y = *reinterpret_cast<unsigned*>(&l);
            Am1[t * 32 + lane] = wv;
        }
    }
    __syncthreads();

    // -------- Stage B: k-split split-bf16 tensor-core contraction --------
    // warp -> (mtile mt, kgroup) ; 8 slices x all 8 n-tiles, partials in regs
    int mt   = wid & 1;
    int kgrp = wid >> 1;                  // 0..7
    int slBase = kgrp * 8;
    int g = lane >> 2, c = lane & 3;
    const float* rowA  = As + (mt * 16 + g) * APAD;
    const float* rowA8 = rowA + 8 * APAD;

    float dacc[NTILES * 4];
    #pragma unroll
    for (int q = 0; q < NTILES * 4; ++q) dacc[q] = 0.f;

    #pragma unroll 1
    for (int sl = slBase; sl < slBase + 8; ++sl) {
        uint4 kb[NTILES];
        #pragma unroll
        for (int nt = 0; nt < NTILES; ++nt)
            kb[nt] = g_kc[(sl * NTILES + nt) * 32 + lane];
        const float* pa = rowA  + 16 * sl + 2 * c;
        const float* pb = rowA8 + 16 * sl + 2 * c;
        uint2 A0 = *(const uint2*)(pa);
        uint2 A1 = *(const uint2*)(pb);
        uint2 A2 = *(const uint2*)(pa + 8);
        uint2 A3 = *(const uint2*)(pb + 8);
        #pragma unroll
        for (int nt = 0; nt < NTILES; ++nt) {
            uint4 kv = kb[nt];
            float* d = dacc + nt * 4;
            mma16816(d, A0.x, A1.x, A2.x, A3.x, kv.x, kv.y);
            mma16816(d, A0.x, A1.x, A2.x, A3.x, kv.z, kv.w);
            mma16816(d, A0.y, A1.y, A2.y, A3.y, kv.x, kv.y);
        }
    }

    // -------- partial reduction through padded smem --------
    __syncthreads();   // all A reads done; safe to overwrite As
    {
        float* base = As + wid * PARTW + lane * 36;
        #pragma unroll
        for (int nt = 0; nt < NTILES; ++nt)
            *(float4*)(base + nt * 4) = *(float4*)(dacc + nt * 4);
    }
    __syncthreads();
    {
        int mtr  = tid >> 8;          // 0..1
        int rem  = tid & 255;
        int ntr  = rem >> 5;          // 0..7
        int lnr  = rem & 31;
        int gr = lnr >> 2, cr = lnr & 3;
        float4 acc = make_float4(0.f, 0.f, 0.f, 0.f);
        #pragma unroll
        for (int k = 0; k < 8; ++k) {
            int w = 2 * k + mtr;
            float4 p = *(float4*)(As + w * PARTW + lnr * 36 + ntr * 4);
            acc.x += p.x; acc.y += p.y; acc.z += p.z; acc.w += p.w;
        }
        int o = ntr * 8 + 2 * cr;
        float2 b = *(const float2*)(bias + o);
        int node0 = nodeBase + mtr * 16 + gr;
        int node8 = node0 + 8;
        if (node0 < n) {
            float2 r = make_float2(acc.x + b.x, acc.y + b.y);
            *(float2*)(out + (size_t)node0 * OUTC + o) = r;
        }
        if (node8 < n) {
            float2 r = make_float2(acc.z + b.x, acc.w + b.y);
            *(float2*)(out + (size_t)node8 * OUTC + o) = r;
        }
    }
}

// ---------------------------------------------------------------------------
extern "C" void kernel_launch(void* const* d_in, const int* in_sizes, int n_in,
                              void* d_out, int out_size) {
    const float* features  = (const float*)d_in[0];
    const int*   receivers = (const int*)  d_in[1];
    const float* relpos    = (const float*)d_in[2];
    const float* wsp       = (const float*)d_in[3];
    const int*   senders   = (const int*)  d_in[4];
    const float* kernelW   = (const float*)d_in[5];
    const float* bias      = (const float*)d_in[6];
    float*       out       = (float*)d_out;

    int n = in_sizes[0] / INC;   // 50000
    int e = in_sizes[1];         // 800000
    int nb = (n + 1023) / 1024;  // 49
    int cntBlocks = (e + 255) / 256;

    cudaFuncSetAttribute(fused_conv_kernel,
                         cudaFuncAttributeMaxDynamicSharedMemorySize, SMEM_BYTES);

    count_and_kcanon<<<cntBlocks + KC_BLOCKS, 256>>>(receivers, e, cntBlocks, kernelW);
    scan_lookback   <<<nb, 1024>>>(n, nb);
    build_records   <<<cntBlocks, 256>>>(receivers, senders, relpos, wsp, e);

    int blocks = (n + MTILE - 1) / MTILE;
    fused_conv_kernel<<<blocks, THREADS, SMEM_BYTES>>>(features, bias, out, n);
}

// round 10
// speedup vs baseline: 1.2042x; 1.2042x over previous
#include <cuda_runtime.h>
#include <cuda_bf16.h>

// ---------------------------------------------------------------------------
// ASCC continuous conv, v8 = v6 skeleton + k-split stage B:
//   L0: count_edges + build_kcanon (merged)
//   L1: decoupled-lookback scan
//   L2: build_records (re-zeros count/pub for next replay)
//   L3: fused kernel (16 nodes/CTA, 256 threads, 2 CTAs/SM):
//       Stage A: reg-double-buffered 256-edge chunks, dual-stream smem RMW
//                (identical to v6 -- proven issue efficiency)
//       Convert: fp32 -> (bf16 hi, lo) in place, float4-vectorized
//       Stage B: K-SPLIT -- warp w owns 8 K-slices x all 8 n-tiles, so each
//                A fragment is loaded exactly once per CTA (8x fewer LDS);
//                partials reduced through padded smem (stride 36).
// ---------------------------------------------------------------------------

#define NMAX    50048
#define EMAX    800000
#define INC     64
#define OUTC    64
#define MTILE   16
#define APAD    1032            // stride % 32 == 8 -> conflict-free LDS.64
#define CHUNK   256
#define FDEPTH  4               // per stream (2 streams)
#define NBMAX   64

#define KSLICES 64
#define NTILES  8

#define SMEM_FLOATS (MTILE * APAD)
#define SMEM_BYTES  (SMEM_FLOATS * 4 + CHUNK * 16 + CHUNK * 8)

#define PARTW   1152            // floats per warp partial region (32 lanes*36)

#define KC_BLOCKS 64            // 16384 / 256

__device__ float4 g_w   [EMAX];
__device__ int2   g_meta[EMAX];
__device__ int    g_count  [NMAX];
__device__ int    g_offsets[NMAX + 1];
__device__ int    g_cursor [NMAX];
__device__ int    g_pub    [NBMAX];          // lookback: aggregate | FLAG
__device__ uint4  g_kc[KSLICES * NTILES * 32];

#define PUB_FLAG 0x40000000

// ---------------------------------------------------------------------------
__device__ __forceinline__ float kfull_val(const float* __restrict__ kernelW,
                                           int k, int nn) {
    int tap = k >> 6, i = k & 63;
    int tx = tap >> 2, ty = tap & 3;
    if (ty < 2) return  kernelW[(tx * 2 + ty) * 4096 + i * 64 + nn];
    else        return -kernelW[((3 - tx) * 2 + (3 - ty)) * 4096 + i * 64 + nn];
}

// L0: blocks [0, cntBlocks) histogram; blocks [cntBlocks, +KC_BLOCKS) K-canon
__global__ void count_and_kcanon(const int* __restrict__ receivers, int e,
                                 int cntBlocks,
                                 const float* __restrict__ kernelW) {
    int b = blockIdx.x;
    if (b < cntBlocks) {
        int i = b * 256 + threadIdx.x;
        if (i < e) atomicAdd(&g_count[receivers[i]], 1);
        return;
    }
    int idx = (b - cntBlocks) * 256 + threadIdx.x;   // 0 .. 16383
    if (idx >= KSLICES * NTILES * 32) return;
    int lane = idx & 31;
    int nt   = (idx >> 5) & 7;
    int s    = idx >> 8;
    int g = lane >> 2, c = lane & 3;
    int nn = nt * 8 + g;
    int k0 = s * 16 + 2 * c;

    float v0 = kfull_val(kernelW, k0,     nn);
    float v1 = kfull_val(kernelW, k0 + 1, nn);
    float v2 = kfull_val(kernelW, k0 + 8, nn);
    float v3 = kfull_val(kernelW, k0 + 9, nn);

    __nv_bfloat162 h01 = __floats2bfloat162_rn(v0, v1);
    __nv_bfloat162 h23 = __floats2bfloat162_rn(v2, v3);
    float h0 = __bfloat162float(__low2bfloat16(h01));
    float h1 = __bfloat162float(__high2bfloat16(h01));
    float h2 = __bfloat162float(__low2bfloat16(h23));
    float h3 = __bfloat162float(__high2bfloat16(h23));
    __nv_bfloat162 l01 = __floats2bfloat162_rn(v0 - h0, v1 - h1);
    __nv_bfloat162 l23 = __floats2bfloat162_rn(v2 - h2, v3 - h3);

    uint4 kv;
    kv.x = *reinterpret_cast<unsigned*>(&h01);
    kv.y = *reinterpret_cast<unsigned*>(&h23);
    kv.z = *reinterpret_cast<unsigned*>(&l01);
    kv.w = *reinterpret_cast<unsigned*>(&l23);
    g_kc[idx] = kv;
}

// ---------------------------------------------------------------------------
// L1: single-kernel scan, decoupled lookback (block b waits only on t < b).
__global__ void scan_lookback(int n, int nb) {
    __shared__ int wsum[32];
    __shared__ int rsum[32];
    int tid = threadIdx.x, lane = tid & 31, wid = tid >> 5;
    int b = blockIdx.x;
    int i = b * 1024 + tid;
    int v = (i < n) ? g_count[i] : 0;
    int x = v;
    #pragma unroll
    for (int d = 1; d < 32; d <<= 1) {
        int y = __shfl_up_sync(0xFFFFFFFFu, x, d);
        if (lane >= d) x += y;
    }
    if (lane == 31) wsum[wid] = x;
    __syncthreads();
    if (wid == 0) {
        int s = wsum[lane];
        #pragma unroll
        for (int d = 1; d < 32; d <<= 1) {
            int y = __shfl_up_sync(0xFFFFFFFFu, s, d);
            if (lane >= d) s += y;
        }
        wsum[lane] = s;
    }
    __syncthreads();
    int aggregate = wsum[31];

    if (tid == 0) atomicExch(&g_pub[b], aggregate | PUB_FLAG);

    int myprev = 0;
    if (tid < b) {
        int pv = atomicAdd(&g_pub[tid], 0);
        while (!(pv & PUB_FLAG)) {
            __nanosleep(64);
            pv = atomicAdd(&g_pub[tid], 0);
        }
        myprev = pv & (PUB_FLAG - 1);
    }
    #pragma unroll
    for (int d = 16; d > 0; d >>= 1)
        myprev += __shfl_down_sync(0xFFFFFFFFu, myprev, d);
    if (lane == 0) rsum[wid] = myprev;
    __syncthreads();
    if (wid == 0) {
        int t = rsum[lane];
        #pragma unroll
        for (int d = 16; d > 0; d >>= 1)
            t += __shfl_down_sync(0xFFFFFFFFu, t, d);
        rsum[0] = t;
    }
    __syncthreads();
    int exclBlock = rsum[0];

    int excl = exclBlock + (wid ? wsum[wid - 1] : 0) + (x - v);
    if (i < n) { g_offsets[i] = excl; g_cursor[i] = excl; }
    if (b == nb - 1 && tid == 0) g_offsets[n] = exclBlock + aggregate;
}

// ---------------------------------------------------------------------------
// L2: scatter records; also re-zero g_count / g_pub for the next replay.
__global__ void build_records(const int*   __restrict__ receivers,
                              const int*   __restrict__ senders,
                              const float* __restrict__ relpos,
                              const float* __restrict__ wsp,
                              int e) {
    int i = blockIdx.x * blockDim.x + threadIdx.x;
    if (i < NMAX)  g_count[i] = 0;
    if (i < NBMAX) g_pub[i]   = 0;
    if (i >= e) return;
    float ws = wsp[0];
    float rx = relpos[2 * i], ry = relpos[2 * i + 1];
    float ux = fminf(fmaxf(rx / ws, -1.0f), 1.0f);
    float uy = fminf(fmaxf(ry / ws, -1.0f), 1.0f);
    float gx = (ux + 1.0f) * 1.5f;
    float gy = (uy + 1.0f) * 1.5f;
    float x0f = fminf(fmaxf(floorf(gx), 0.0f), 2.0f);
    float y0f = fminf(fmaxf(floorf(gy), 0.0f), 2.0f);
    float fx = gx - x0f, fy = gy - y0f;
    float r2 = ux * ux + uy * uy;
    float wm = fmaxf(1.0f - r2, 0.0f);
    float win = wm * wm * wm;
    int x0 = (int)x0f, y0 = (int)y0f;
    int t0 = x0 * 4 + y0;

    float4 w = make_float4((1.0f - fx) * (1.0f - fy) * win,
                           (1.0f - fx) * fy          * win,
                           fx          * (1.0f - fy) * win,
                           fx          * fy          * win);
    int taps = t0 | ((t0 + 1) << 8) | ((t0 + 4) << 16) | ((t0 + 5) << 24);

    int r = receivers[i];
    int slot = atomicAdd(&g_cursor[r], 1);
    g_w[slot]    = w;
    g_meta[slot] = make_int2(senders[i], taps);
}

// ---------------------------------------------------------------------------
__device__ __forceinline__ void mma16816(float* d,
        unsigned a0, unsigned a1, unsigned a2, unsigned a3,
        unsigned b0, unsigned b1) {
    asm volatile(
        "mma.sync.aligned.m16n8k16.row.col.f32.bf16.bf16.f32 "
        "{%0,%1,%2,%3}, {%4,%5,%6,%7}, {%8,%9}, {%0,%1,%2,%3};"
        : "+f"(d[0]), "+f"(d[1]), "+f"(d[2]), "+f"(d[3])
        : "r"(a0), "r"(a1), "r"(a2), "r"(a3), "r"(b0), "r"(b1));
}

__device__ __forceinline__ void apply_edge(float* Am, int lane,
                                           float4 w4, int tps, float2 f) {
    float2* p0 = (float2*)(Am + (tps         & 0xFF) * 64) + lane;
    float2* p1 = (float2*)(Am + ((tps >>  8) & 0xFF) * 64) + lane;
    float2* p2 = (float2*)(Am + ((tps >> 16) & 0xFF) * 64) + lane;
    float2* p3 = (float2*)(Am + ((tps >> 24) & 0xFF) * 64) + lane;
    float2 v0 = *p0, v1 = *p1, v2 = *p2, v3 = *p3;
    v0.x += w4.x * f.x; v0.y += w4.x * f.y;
    v1.x += w4.y * f.x; v1.y += w4.y * f.y;
    v2.x += w4.z * f.x; v2.y += w4.z * f.y;
    v3.x += w4.w * f.x; v3.y += w4.w * f.y;
    *p0 = v0; *p1 = v1; *p2 = v2; *p3 = v3;
}

__global__ __launch_bounds__(256, 2)
void fused_conv_kernel(const float* __restrict__ features,
                       const float* __restrict__ bias,
                       float*       __restrict__ out,
                       int n) {
    extern __shared__ float smem[];
    float*  As = smem;                                   // MTILE * APAD
    float4* ws = (float4*)(smem + SMEM_FLOATS);          // CHUNK
    int2*   ms = (int2*)((char*)ws + CHUNK * 16);        // CHUNK

    int tid  = threadIdx.x;
    int lane = tid & 31, wid = tid >> 5;
    int nodeBase = blockIdx.x * MTILE;

    // zero accumulator tile (float4)
    {
        float4 z = make_float4(0.f, 0.f, 0.f, 0.f);
        float4* Az = (float4*)As;
        for (int i = tid; i < SMEM_FLOATS / 4; i += 256) Az[i] = z;
    }

    int n0 = min(nodeBase + 2 * wid,     n);
    int n1 = min(nodeBase + 2 * wid + 1, n);
    int n2 = min(nodeBase + 2 * wid + 2, n);
    int s   = g_offsets[n0];
    int mid = g_offsets[n1];
    int e2  = g_offsets[n2];
    float* Am0 = As + (2 * wid) * APAD;
    float* Am1 = Am0 + APAD;

    int o0 = g_offsets[nodeBase];
    int oE = g_offsets[min(nodeBase + MTILE, n)];

    // stage chunk 0 into registers (1 edge/thread)
    float4 rw = make_float4(0.f, 0.f, 0.f, 0.f);
    int2   rm = make_int2(0, 0);
    if (o0 + tid < oE) { rw = g_w[o0 + tid]; rm = g_meta[o0 + tid]; }

    // -------- Stage A: dual-stream apply over reg-double-buffered chunks ----
    for (int cs = o0; cs < oE; cs += CHUNK) {
        if (cs + tid < oE) { ws[tid] = rw; ms[tid] = rm; }
        __syncthreads();
        int nx = cs + CHUNK + tid;
        if (nx < oE) { rw = g_w[nx]; rm = g_meta[nx]; }

        int ce = min(cs + CHUNK, oE);
        int ja = max(s,   cs), ea = min(mid, ce);   // stream A -> Am0
        int jb = max(mid, cs), eb = min(e2,  ce);   // stream B -> Am1
        int cnt = max(ea - ja, eb - jb);
        if (cnt > 0) {
            float2 fa[FDEPTH], fb[FDEPTH];
            #pragma unroll
            for (int d = 0; d < FDEPTH; ++d) {
                if (ja + d < ea)
                    fa[d] = *(const float2*)(features +
                        (size_t)ms[ja + d - cs].x * INC + lane * 2);
                if (jb + d < eb)
                    fb[d] = *(const float2*)(features +
                        (size_t)ms[jb + d - cs].x * INC + lane * 2);
            }
            #pragma unroll 4
            for (int k = 0; k < cnt; ++k) {
                int d = k & (FDEPTH - 1);
                if (ja + k < ea) {
                    int li = ja + k - cs;
                    float4 w4 = ws[li];
                    int   tps = ms[li].y;
                    float2 f  = fa[d];
                    int jn = ja + k + FDEPTH;
                    if (jn < ea)
                        fa[d] = *(const float2*)(features +
                            (size_t)ms[jn - cs].x * INC + lane * 2);
                    apply_edge(Am0, lane, w4, tps, f);
                }
                if (jb + k < eb) {
                    int li = jb + k - cs;
                    float4 w4 = ws[li];
                    int   tps = ms[li].y;
                    float2 f  = fb[d];
                    int jn = jb + k + FDEPTH;
                    if (jn < eb)
                        fb[d] = *(const float2*)(features +
                            (size_t)ms[jn - cs].x * INC + lane * 2);
                    apply_edge(Am1, lane, w4, tps, f);
                }
            }
        }
        __syncthreads();
    }
    __syncthreads();

    // -------- Convert A in place (float4 vectorized) --------
    for (int i = tid; i < MTILE * 256; i += 256) {
        int m = i >> 8;
        int t = i & 255;
        float* p = As + m * APAD + 4 * t;
        float4 v = *(float4*)p;
        __nv_bfloat162 h0 = __floats2bfloat162_rn(v.x, v.y);
        __nv_bfloat162 h1 = __floats2bfloat162_rn(v.z, v.w);
        float a0 = __bfloat162float(__low2bfloat16(h0));
        float a1 = __bfloat162float(__high2bfloat16(h0));
        float a2 = __bfloat162float(__low2bfloat16(h1));
        float a3 = __bfloat162float(__high2bfloat16(h1));
        __nv_bfloat162 l0 = __floats2bfloat162_rn(v.x - a0, v.y - a1);
        __nv_bfloat162 l1 = __floats2bfloat162_rn(v.z - a2, v.w - a3);
        uint4 w;
        w.x = *reinterpret_cast<unsigned*>(&h0);
        w.y = *reinterpret_cast<unsigned*>(&l0);
        w.z = *reinterpret_cast<unsigned*>(&h1);
        w.w = *reinterpret_cast<unsigned*>(&l1);
        *(uint4*)p = w;
    }
    __syncthreads();

    // -------- Stage B: K-SPLIT split-bf16 tensor-core contraction --------
    // warp wid = kgroup: slices [8*wid, 8*wid+8), all 8 n-tiles.
    // Each A fragment is loaded by exactly one warp (8x fewer LDS than v6).
    int g = lane >> 2, c = lane & 3;
    const float* rowA  = As + g * APAD;
    const float* rowA8 = rowA + 8 * APAD;

    float dacc[NTILES * 4];
    #pragma unroll
    for (int q = 0; q < NTILES * 4; ++q) dacc[q] = 0.f;

    #pragma unroll 1
    for (int i = 0; i < 8; ++i) {
        int sl = wid * 8 + i;
        uint4 kb[NTILES];
        #pragma unroll
        for (int nt = 0; nt < NTILES; ++nt)
            kb[nt] = g_kc[(sl * NTILES + nt) * 32 + lane];
        const float* pa = rowA  + 16 * sl + 2 * c;
        const float* pb = rowA8 + 16 * sl + 2 * c;
        uint2 A0 = *(const uint2*)(pa);
        uint2 A1 = *(const uint2*)(pb);
        uint2 A2 = *(const uint2*)(pa + 8);
        uint2 A3 = *(const uint2*)(pb + 8);
        #pragma unroll
        for (int nt = 0; nt < NTILES; ++nt) {
            uint4 kv = kb[nt];
            float* d = dacc + nt * 4;
            mma16816(d, A0.x, A1.x, A2.x, A3.x, kv.x, kv.y);
            mma16816(d, A0.x, A1.x, A2.x, A3.x, kv.z, kv.w);
            mma16816(d, A0.y, A1.y, A2.y, A3.y, kv.x, kv.y);
        }
    }

    // -------- partial reduction through padded smem --------
    __syncthreads();   // all A reads done; safe to overwrite As
    {
        float* base = As + wid * PARTW + lane * 36;
        #pragma unroll
        for (int nt = 0; nt < NTILES; ++nt)
            *(float4*)(base + nt * 4) = *(float4*)(dacc + nt * 4);
    }
    __syncthreads();
    {
        int ntr = tid >> 5;           // 0..7 (n-tile)
        int lnr = tid & 31;
        int gr = lnr >> 2, cr = lnr & 3;
        float4 acc = make_float4(0.f, 0.f, 0.f, 0.f);
        #pragma unroll
        for (int w = 0; w < 8; ++w) {
            float4 p = *(float4*)(As + w * PARTW + lnr * 36 + ntr * 4);
            acc.x += p.x; acc.y += p.y; acc.z += p.z; acc.w += p.w;
        }
        int o = ntr * 8 + 2 * cr;
        float2 b = *(const float2*)(bias + o);
        int node0 = nodeBase + gr;
        int node8 = node0 + 8;
        if (node0 < n) {
            float2 r = make_float2(acc.x + b.x, acc.y + b.y);
            *(float2*)(out + (size_t)node0 * OUTC + o) = r;
        }
        if (node8 < n) {
            float2 r = make_float2(acc.z + b.x, acc.w + b.y);
            *(float2*)(out + (size_t)node8 * OUTC + o) = r;
        }
    }
}

// ---------------------------------------------------------------------------
extern "C" void kernel_launch(void* const* d_in, const int* in_sizes, int n_in,
                              void* d_out, int out_size) {
    const float* features  = (const float*)d_in[0];
    const int*   receivers = (const int*)  d_in[1];
    const float* relpos    = (const float*)d_in[2];
    const float* wsp       = (const float*)d_in[3];
    const int*   senders   = (const int*)  d_in[4];
    const float* kernelW   = (const float*)d_in[5];
    const float* bias      = (const float*)d_in[6];
    float*       out       = (float*)d_out;

    int n = in_sizes[0] / INC;   // 50000
    int e = in_sizes[1];         // 800000
    int nb = (n + 1023) / 1024;  // 49
    int cntBlocks = (e + 255) / 256;

    cudaFuncSetAttribute(fused_conv_kernel,
                         cudaFuncAttributeMaxDynamicSharedMemorySize, SMEM_BYTES);

    count_and_kcanon<<<cntBlocks + KC_BLOCKS, 256>>>(receivers, e, cntBlocks, kernelW);
    scan_lookback   <<<nb, 1024>>>(n, nb);
    build_records   <<<cntBlocks, 256>>>(receivers, senders, relpos, wsp, e);

    int blocks = (n + MTILE - 1) / MTILE;
    fused_conv_kernel<<<blocks, 256, SMEM_BYTES>>>(features, bias, out, n);
}

// round 11
// speedup vs baseline: 1.3594x; 1.1288x over previous
#include <cuda_runtime.h>
#include <cuda_bf16.h>

// ---------------------------------------------------------------------------
// ASCC continuous conv, v9 = v8 + 3 CTAs/SM restored:
//   - __launch_bounds__(256, 3) caps regs at 85 (v8's 90 regs silently cost
//     the third resident CTA; v6 ran 3 CTAs at 77 regs)
//   - stage B K fragments loaded in two batches of 4 n-tiles (kb[4]) to cut
//     live registers; A fragments persist across both batches
//   Pipeline (4 launches):
//   L0: count_edges + build_kcanon (merged)
//   L1: decoupled-lookback scan
//   L2: build_records (re-zeros count/pub for next replay)
//   L3: fused kernel (16 nodes/CTA, 256 threads, 3 CTAs/SM):
//       Stage A: reg-double-buffered 256-edge chunks, dual-stream smem RMW
//       Convert: fp32 -> (bf16 hi, lo) in place, float4-vectorized
//       Stage B: K-SPLIT (warp = kgroup, A fragments read once per CTA),
//                partials reduced through padded smem (stride 36)
// ---------------------------------------------------------------------------

#define NMAX    50048
#define EMAX    800000
#define INC     64
#define OUTC    64
#define MTILE   16
#define APAD    1032            // stride % 32 == 8 -> conflict-free LDS.64
#define CHUNK   256
#define FDEPTH  4               // per stream (2 streams)
#define NBMAX   64

#define KSLICES 64
#define NTILES  8

#define SMEM_FLOATS (MTILE * APAD)
#define SMEM_BYTES  (SMEM_FLOATS * 4 + CHUNK * 16 + CHUNK * 8)

#define PARTW   1152            // floats per warp partial region (32 lanes*36)

#define KC_BLOCKS 64            // 16384 / 256

__device__ float4 g_w   [EMAX];
__device__ int2   g_meta[EMAX];
__device__ int    g_count  [NMAX];
__device__ int    g_offsets[NMAX + 1];
__device__ int    g_cursor [NMAX];
__device__ int    g_pub    [NBMAX];          // lookback: aggregate | FLAG
__device__ uint4  g_kc[KSLICES * NTILES * 32];

#define PUB_FLAG 0x40000000

// ---------------------------------------------------------------------------
__device__ __forceinline__ float kfull_val(const float* __restrict__ kernelW,
                                           int k, int nn) {
    int tap = k >> 6, i = k & 63;
    int tx = tap >> 2, ty = tap & 3;
    if (ty < 2) return  kernelW[(tx * 2 + ty) * 4096 + i * 64 + nn];
    else        return -kernelW[((3 - tx) * 2 + (3 - ty)) * 4096 + i * 64 + nn];
}

// L0: blocks [0, cntBlocks) histogram; blocks [cntBlocks, +KC_BLOCKS) K-canon
__global__ void count_and_kcanon(const int* __restrict__ receivers, int e,
                                 int cntBlocks,
                                 const float* __restrict__ kernelW) {
    int b = blockIdx.x;
    if (b < cntBlocks) {
        int i = b * 256 + threadIdx.x;
        if (i < e) atomicAdd(&g_count[receivers[i]], 1);
        return;
    }
    int idx = (b - cntBlocks) * 256 + threadIdx.x;   // 0 .. 16383
    if (idx >= KSLICES * NTILES * 32) return;
    int lane = idx & 31;
    int nt   = (idx >> 5) & 7;
    int s    = idx >> 8;
    int g = lane >> 2, c = lane & 3;
    int nn = nt * 8 + g;
    int k0 = s * 16 + 2 * c;

    float v0 = kfull_val(kernelW, k0,     nn);
    float v1 = kfull_val(kernelW, k0 + 1, nn);
    float v2 = kfull_val(kernelW, k0 + 8, nn);
    float v3 = kfull_val(kernelW, k0 + 9, nn);

    __nv_bfloat162 h01 = __floats2bfloat162_rn(v0, v1);
    __nv_bfloat162 h23 = __floats2bfloat162_rn(v2, v3);
    float h0 = __bfloat162float(__low2bfloat16(h01));
    float h1 = __bfloat162float(__high2bfloat16(h01));
    float h2 = __bfloat162float(__low2bfloat16(h23));
    float h3 = __bfloat162float(__high2bfloat16(h23));
    __nv_bfloat162 l01 = __floats2bfloat162_rn(v0 - h0, v1 - h1);
    __nv_bfloat162 l23 = __floats2bfloat162_rn(v2 - h2, v3 - h3);

    uint4 kv;
    kv.x = *reinterpret_cast<unsigned*>(&h01);
    kv.y = *reinterpret_cast<unsigned*>(&h23);
    kv.z = *reinterpret_cast<unsigned*>(&l01);
    kv.w = *reinterpret_cast<unsigned*>(&l23);
    g_kc[idx] = kv;
}

// ---------------------------------------------------------------------------
// L1: single-kernel scan, decoupled lookback (block b waits only on t < b).
__global__ void scan_lookback(int n, int nb) {
    __shared__ int wsum[32];
    __shared__ int rsum[32];
    int tid = threadIdx.x, lane = tid & 31, wid = tid >> 5;
    int b = blockIdx.x;
    int i = b * 1024 + tid;
    int v = (i < n) ? g_count[i] : 0;
    int x = v;
    #pragma unroll
    for (int d = 1; d < 32; d <<= 1) {
        int y = __shfl_up_sync(0xFFFFFFFFu, x, d);
        if (lane >= d) x += y;
    }
    if (lane == 31) wsum[wid] = x;
    __syncthreads();
    if (wid == 0) {
        int s = wsum[lane];
        #pragma unroll
        for (int d = 1; d < 32; d <<= 1) {
            int y = __shfl_up_sync(0xFFFFFFFFu, s, d);
            if (lane >= d) s += y;
        }
        wsum[lane] = s;
    }
    __syncthreads();
    int aggregate = wsum[31];

    if (tid == 0) atomicExch(&g_pub[b], aggregate | PUB_FLAG);

    int myprev = 0;
    if (tid < b) {
        int pv = atomicAdd(&g_pub[tid], 0);
        while (!(pv & PUB_FLAG)) {
            __nanosleep(64);
            pv = atomicAdd(&g_pub[tid], 0);
        }
        myprev = pv & (PUB_FLAG - 1);
    }
    #pragma unroll
    for (int d = 16; d > 0; d >>= 1)
        myprev += __shfl_down_sync(0xFFFFFFFFu, myprev, d);
    if (lane == 0) rsum[wid] = myprev;
    __syncthreads();
    if (wid == 0) {
        int t = rsum[lane];
        #pragma unroll
        for (int d = 16; d > 0; d >>= 1)
            t += __shfl_down_sync(0xFFFFFFFFu, t, d);
        rsum[0] = t;
    }
    __syncthreads();
    int exclBlock = rsum[0];

    int excl = exclBlock + (wid ? wsum[wid - 1] : 0) + (x - v);
    if (i < n) { g_offsets[i] = excl; g_cursor[i] = excl; }
    if (b == nb - 1 && tid == 0) g_offsets[n] = exclBlock + aggregate;
}

// ---------------------------------------------------------------------------
// L2: scatter records; also re-zero g_count / g_pub for the next replay.
__global__ void build_records(const int*   __restrict__ receivers,
                              const int*   __restrict__ senders,
                              const float* __restrict__ relpos,
                              const float* __restrict__ wsp,
                              int e) {
    int i = blockIdx.x * blockDim.x + threadIdx.x;
    if (i < NMAX)  g_count[i] = 0;
    if (i < NBMAX) g_pub[i]   = 0;
    if (i >= e) return;
    float ws = wsp[0];
    float rx = relpos[2 * i], ry = relpos[2 * i + 1];
    float ux = fminf(fmaxf(rx / ws, -1.0f), 1.0f);
    float uy = fminf(fmaxf(ry / ws, -1.0f), 1.0f);
    float gx = (ux + 1.0f) * 1.5f;
    float gy = (uy + 1.0f) * 1.5f;
    float x0f = fminf(fmaxf(floorf(gx), 0.0f), 2.0f);
    float y0f = fminf(fmaxf(floorf(gy), 0.0f), 2.0f);
    float fx = gx - x0f, fy = gy - y0f;
    float r2 = ux * ux + uy * uy;
    float wm = fmaxf(1.0f - r2, 0.0f);
    float win = wm * wm * wm;
    int x0 = (int)x0f, y0 = (int)y0f;
    int t0 = x0 * 4 + y0;

    float4 w = make_float4((1.0f - fx) * (1.0f - fy) * win,
                           (1.0f - fx) * fy          * win,
                           fx          * (1.0f - fy) * win,
                           fx          * fy          * win);
    int taps = t0 | ((t0 + 1) << 8) | ((t0 + 4) << 16) | ((t0 + 5) << 24);

    int r = receivers[i];
    int slot = atomicAdd(&g_cursor[r], 1);
    g_w[slot]    = w;
    g_meta[slot] = make_int2(senders[i], taps);
}

// ---------------------------------------------------------------------------
__device__ __forceinline__ void mma16816(float* d,
        unsigned a0, unsigned a1, unsigned a2, unsigned a3,
        unsigned b0, unsigned b1) {
    asm volatile(
        "mma.sync.aligned.m16n8k16.row.col.f32.bf16.bf16.f32 "
        "{%0,%1,%2,%3}, {%4,%5,%6,%7}, {%8,%9}, {%0,%1,%2,%3};"
        : "+f"(d[0]), "+f"(d[1]), "+f"(d[2]), "+f"(d[3])
        : "r"(a0), "r"(a1), "r"(a2), "r"(a3), "r"(b0), "r"(b1));
}

__device__ __forceinline__ void apply_edge(float* Am, int lane,
                                           float4 w4, int tps, float2 f) {
    float2* p0 = (float2*)(Am + (tps         & 0xFF) * 64) + lane;
    float2* p1 = (float2*)(Am + ((tps >>  8) & 0xFF) * 64) + lane;
    float2* p2 = (float2*)(Am + ((tps >> 16) & 0xFF) * 64) + lane;
    float2* p3 = (float2*)(Am + ((tps >> 24) & 0xFF) * 64) + lane;
    float2 v0 = *p0, v1 = *p1, v2 = *p2, v3 = *p3;
    v0.x += w4.x * f.x; v0.y += w4.x * f.y;
    v1.x += w4.y * f.x; v1.y += w4.y * f.y;
    v2.x += w4.z * f.x; v2.y += w4.z * f.y;
    v3.x += w4.w * f.x; v3.y += w4.w * f.y;
    *p0 = v0; *p1 = v1; *p2 = v2; *p3 = v3;
}

__global__ __launch_bounds__(256, 3)
void fused_conv_kernel(const float* __restrict__ features,
                       const float* __restrict__ bias,
                       float*       __restrict__ out,
                       int n) {
    extern __shared__ float smem[];
    float*  As = smem;                                   // MTILE * APAD
    float4* ws = (float4*)(smem + SMEM_FLOATS);          // CHUNK
    int2*   ms = (int2*)((char*)ws + CHUNK * 16);        // CHUNK

    int tid  = threadIdx.x;
    int lane = tid & 31, wid = tid >> 5;
    int nodeBase = blockIdx.x * MTILE;

    // zero accumulator tile (float4)
    {
        float4 z = make_float4(0.f, 0.f, 0.f, 0.f);
        float4* Az = (float4*)As;
        for (int i = tid; i < SMEM_FLOATS / 4; i += 256) Az[i] = z;
    }

    int n0 = min(nodeBase + 2 * wid,     n);
    int n1 = min(nodeBase + 2 * wid + 1, n);
    int n2 = min(nodeBase + 2 * wid + 2, n);
    int s   = g_offsets[n0];
    int mid = g_offsets[n1];
    int e2  = g_offsets[n2];
    float* Am0 = As + (2 * wid) * APAD;
    float* Am1 = Am0 + APAD;

    int o0 = g_offsets[nodeBase];
    int oE = g_offsets[min(nodeBase + MTILE, n)];

    // stage chunk 0 into registers (1 edge/thread)
    float4 rw = make_float4(0.f, 0.f, 0.f, 0.f);
    int2   rm = make_int2(0, 0);
    if (o0 + tid < oE) { rw = g_w[o0 + tid]; rm = g_meta[o0 + tid]; }

    // -------- Stage A: dual-stream apply over reg-double-buffered chunks ----
    for (int cs = o0; cs < oE; cs += CHUNK) {
        if (cs + tid < oE) { ws[tid] = rw; ms[tid] = rm; }
        __syncthreads();
        int nx = cs + CHUNK + tid;
        if (nx < oE) { rw = g_w[nx]; rm = g_meta[nx]; }

        int ce = min(cs + CHUNK, oE);
        int ja = max(s,   cs), ea = min(mid, ce);   // stream A -> Am0
        int jb = max(mid, cs), eb = min(e2,  ce);   // stream B -> Am1
        int cnt = max(ea - ja, eb - jb);
        if (cnt > 0) {
            float2 fa[FDEPTH], fb[FDEPTH];
            #pragma unroll
            for (int d = 0; d < FDEPTH; ++d) {
                if (ja + d < ea)
                    fa[d] = *(const float2*)(features +
                        (size_t)ms[ja + d - cs].x * INC + lane * 2);
                if (jb + d < eb)
                    fb[d] = *(const float2*)(features +
                        (size_t)ms[jb + d - cs].x * INC + lane * 2);
            }
            #pragma unroll 4
            for (int k = 0; k < cnt; ++k) {
                int d = k & (FDEPTH - 1);
                if (ja + k < ea) {
                    int li = ja + k - cs;
                    float4 w4 = ws[li];
                    int   tps = ms[li].y;
                    float2 f  = fa[d];
                    int jn = ja + k + FDEPTH;
                    if (jn < ea)
                        fa[d] = *(const float2*)(features +
                            (size_t)ms[jn - cs].x * INC + lane * 2);
                    apply_edge(Am0, lane, w4, tps, f);
                }
                if (jb + k < eb) {
                    int li = jb + k - cs;
                    float4 w4 = ws[li];
                    int   tps = ms[li].y;
                    float2 f  = fb[d];
                    int jn = jb + k + FDEPTH;
                    if (jn < eb)
                        fb[d] = *(const float2*)(features +
                            (size_t)ms[jn - cs].x * INC + lane * 2);
                    apply_edge(Am1, lane, w4, tps, f);
                }
            }
        }
        __syncthreads();
    }
    __syncthreads();

    // -------- Convert A in place (float4 vectorized) --------
    for (int i = tid; i < MTILE * 256; i += 256) {
        int m = i >> 8;
        int t = i & 255;
        float* p = As + m * APAD + 4 * t;
        float4 v = *(float4*)p;
        __nv_bfloat162 h0 = __floats2bfloat162_rn(v.x, v.y);
        __nv_bfloat162 h1 = __floats2bfloat162_rn(v.z, v.w);
        float a0 = __bfloat162float(__low2bfloat16(h0));
        float a1 = __bfloat162float(__high2bfloat16(h0));
        float a2 = __bfloat162float(__low2bfloat16(h1));
        float a3 = __bfloat162float(__high2bfloat16(h1));
        __nv_bfloat162 l0 = __floats2bfloat162_rn(v.x - a0, v.y - a1);
        __nv_bfloat162 l1 = __floats2bfloat162_rn(v.z - a2, v.w - a3);
        uint4 w;
        w.x = *reinterpret_cast<unsigned*>(&h0);
        w.y = *reinterpret_cast<unsigned*>(&l0);
        w.z = *reinterpret_cast<unsigned*>(&h1);
        w.w = *reinterpret_cast<unsigned*>(&l1);
        *(uint4*)p = w;
    }
    __syncthreads();

    // -------- Stage B: K-SPLIT split-bf16 tensor-core contraction --------
    // warp wid = kgroup: slices [8*wid, 8*wid+8), all 8 n-tiles in two
    // 4-tile batches (kb[4] keeps live regs under the 85-reg/3-CTA cap).
    int g = lane >> 2, c = lane & 3;
    const float* rowA  = As + g * APAD;
    const float* rowA8 = rowA + 8 * APAD;

    float dacc[NTILES * 4];
    #pragma unroll
    for (int q = 0; q < NTILES * 4; ++q) dacc[q] = 0.f;

    #pragma unroll 1
    for (int i = 0; i < 8; ++i) {
        int sl = wid * 8 + i;
        const float* pa = rowA  + 16 * sl + 2 * c;
        const float* pb = rowA8 + 16 * sl + 2 * c;
        uint2 A0 = *(const uint2*)(pa);
        uint2 A1 = *(const uint2*)(pb);
        uint2 A2 = *(const uint2*)(pa + 8);
        uint2 A3 = *(const uint2*)(pb + 8);
        #pragma unroll
        for (int h = 0; h < 2; ++h) {
            uint4 kb[4];
            #pragma unroll
            for (int j = 0; j < 4; ++j)
                kb[j] = g_kc[(sl * NTILES + h * 4 + j) * 32 + lane];
            #pragma unroll
            for (int j = 0; j < 4; ++j) {
                float* d = dacc + (h * 4 + j) * 4;
                mma16816(d, A0.x, A1.x, A2.x, A3.x, kb[j].x, kb[j].y);
                mma16816(d, A0.x, A1.x, A2.x, A3.x, kb[j].z, kb[j].w);
                mma16816(d, A0.y, A1.y, A2.y, A3.y, kb[j].x, kb[j].y);
            }
        }
    }

    // -------- partial reduction through padded smem --------
    __syncthreads();   // all A reads done; safe to overwrite As
    {
        float* base = As + wid * PARTW + lane * 36;
        #pragma unroll
        for (int nt = 0; nt < NTILES; ++nt)
            *(float4*)(base + nt * 4) = *(float4*)(dacc + nt * 4);
    }
    __syncthreads();
    {
        int ntr = tid >> 5;           // 0..7 (n-tile)
        int lnr = tid & 31;
        int gr = lnr >> 2, cr = lnr & 3;
        float4 acc = make_float4(0.f, 0.f, 0.f, 0.f);
        #pragma unroll
        for (int w = 0; w < 8; ++w) {
            float4 p = *(float4*)(As + w * PARTW + lnr * 36 + ntr * 4);
            acc.x += p.x; acc.y += p.y; acc.z += p.z; acc.w += p.w;
        }
        int o = ntr * 8 + 2 * cr;
        float2 b = *(const float2*)(bias + o);
        int node0 = nodeBase + gr;
        int node8 = node0 + 8;
        if (node0 < n) {
            float2 r = make_float2(acc.x + b.x, acc.y + b.y);
            *(float2*)(out + (size_t)node0 * OUTC + o) = r;
        }
        if (node8 < n) {
            float2 r = make_float2(acc.z + b.x, acc.w + b.y);
            *(float2*)(out + (size_t)node8 * OUTC + o) = r;
        }
    }
}

// ---------------------------------------------------------------------------
extern "C" void kernel_launch(void* const* d_in, const int* in_sizes, int n_in,
                              void* d_out, int out_size) {
    const float* features  = (const float*)d_in[0];
    const int*   receivers = (const int*)  d_in[1];
    const float* relpos    = (const float*)d_in[2];
    const float* wsp       = (const float*)d_in[3];
    const int*   senders   = (const int*)  d_in[4];
    const float* kernelW   = (const float*)d_in[5];
    const float* bias      = (const float*)d_in[6];
    float*       out       = (float*)d_out;

    int n = in_sizes[0] / INC;   // 50000
    int e = in_sizes[1];         // 800000
    int nb = (n + 1023) / 1024;  // 49
    int cntBlocks = (e + 255) / 256;

    cudaFuncSetAttribute(fused_conv_kernel,
                         cudaFuncAttributeMaxDynamicSharedMemorySize, SMEM_BYTES);

    count_and_kcanon<<<cntBlocks + KC_BLOCKS, 256>>>(receivers, e, cntBlocks, kernelW);
    scan_lookback   <<<nb, 1024>>>(n, nb);
    build_records   <<<cntBlocks, 256>>>(receivers, senders, relpos, wsp, e);

    int blocks = (n + MTILE - 1) / MTILE;
    fused_conv_kernel<<<blocks, 256, SMEM_BYTES>>>(features, bias, out, n);
}